// round 9
// baseline (speedup 1.0000x reference)
#include <cuda_runtime.h>
#include <cuda_bf16.h>

// PEPS 6x6, D=4, phys=2, batch=1024.
// Split each config at the row2|row3 bond cut into two INDEPENDENT half-tasks:
//   top    = rows 0,1,2 contracted downward  (even blockIdx)
//   bottom = rows 5,4,3 contracted upward    (odd blockIdx, u/d strides swapped)
// amp = dot(V_top, V_bot) over the 4096 cut-bond states. 2048 uniform tasks
// over 296 CTA slots -> makespan 3.5 config-units vs 4 (kills the 13.5% wave
// quantization tail of the 1024-CTA version).
// Interior engine = round-8 proven code (fma.rn.f32x2, m4n8 blocking, 2 CTAs/SM).

#define NT 512

typedef unsigned long long u64;

__device__ float    g_vtop[1024 * 4096];
__device__ unsigned g_flag[1024];

__device__ __forceinline__ u64 pk(float v) {
    u64 r;
    asm("mov.b64 %0, {%1, %1};" : "=l"(r) : "f"(v));
    return r;
}
__device__ __forceinline__ void fma2(u64& d, u64 a, u64 b) {
    asm("fma.rn.f32x2 %0, %1, %2, %0;" : "+l"(d) : "l"(a), "l"(b));
}
__device__ __forceinline__ float2 upk(u64 v) {
    float2 r;
    asm("mov.b64 {%0, %1}, %2;" : "=f"(r.x), "=f"(r.y) : "l"(v));
    return r;
}

// Boundary-row step, all shape parameters compile-time.
template <int F, int K, int N, int PU, int UD, int SRIN>
__device__ __forceinline__ void step_b(
    float* __restrict__ W, const float* __restrict__ A, int tid)
{
    constexpr int TOTAL = N * F;
    constexpr int NOUT = (TOTAL + NT - 1) / NT;
    float accl[NOUT];
    int cnt = 0;
    for (int o = tid; o < TOTAL; o += NT) {
        const int n = o / F;
        const int m = o - n * F;
        const int dp = m / PU;
        const int ur = m - dp * PU;
        const int inb = dp * UD * PU + ur;
        float s = 0.f;
#pragma unroll
        for (int k = 0; k < K; ++k) {
            const int rin = k / UD;
            const int u = k - rin * UD;
            s = fmaf(W[inb + rin * SRIN + u * PU], A[k * N + n], s);
        }
        accl[cnt++] = s;
    }
    __syncthreads();
    cnt = 0;
    for (int o = tid; o < TOTAL; o += NT) {
        const int n = o / F;
        const int m = o - n * F;
        W[n * F + m] = accl[cnt++];
    }
    __syncthreads();
}

// Interior rows, steps 0..4 (round-4/8 proven codegen).
template <int K, int PSH>
__device__ __forceinline__ void step_fast_vec(
    float* __restrict__ W, const float* __restrict__ A, int tid)
{
    const int g = tid >> 8;           // n-group: n = 8g..8g+7
    const int t = tid & 255;
    const int mb = t << 2;            // m-vec base
    const int dp = mb >> PSH;
    const int ur = mb & ((1 << PSH) - 1);
    const int inb = (dp << (PSH + 2)) + ur;

    u64 acc[8][2];
#pragma unroll
    for (int n = 0; n < 8; ++n) { acc[n][0] = 0ull; acc[n][1] = 0ull; }

#pragma unroll
    for (int k = 0; k < K; ++k) {
        const int off = (k >> 2) * 4096 + ((k & 3) << PSH);
        const ulonglong2 xv = *(const ulonglong2*)(W + inb + off);
        const float4 alo = *(const float4*)(A + k * 16 + g * 8);
        const float4 ahi = *(const float4*)(A + k * 16 + g * 8 + 4);
        const float av[8] = { alo.x, alo.y, alo.z, alo.w,
                              ahi.x, ahi.y, ahi.z, ahi.w };
#pragma unroll
        for (int n = 0; n < 8; ++n) {
            const u64 a2 = pk(av[n]);
            fma2(acc[n][0], xv.x, a2);
            fma2(acc[n][1], xv.y, a2);
        }
    }

    __syncthreads();
#pragma unroll
    for (int n = 0; n < 8; ++n) {
        ulonglong2 o;
        o.x = acc[n][0];
        o.y = acc[n][1];
        *(ulonglong2*)(W + (g * 8 + n) * 1024 + mb) = o;
    }
    __syncthreads();
}

// Interior rows, step 5: F=1024, N=4, K=16 (input layout rin*4096 + m*4 + u).
__device__ __forceinline__ void step_fast_last(
    float* __restrict__ W, const float* __restrict__ A, int tid)
{
    const int m0 = tid * 2;
    u64 acc[2][2];
    acc[0][0] = acc[0][1] = acc[1][0] = acc[1][1] = 0ull;

#pragma unroll
    for (int rin = 0; rin < 4; ++rin) {
        const float4 xv0 = *(const float4*)(W + m0 * 4 + rin * 4096);
        const float4 xv1 = *(const float4*)(W + (m0 + 1) * 4 + rin * 4096);
#pragma unroll
        for (int u = 0; u < 4; ++u) {
            const float x0 = (u == 0) ? xv0.x : (u == 1) ? xv0.y : (u == 2) ? xv0.z : xv0.w;
            const float x1 = (u == 0) ? xv1.x : (u == 1) ? xv1.y : (u == 2) ? xv1.z : xv1.w;
            const ulonglong2 a2 = *(const ulonglong2*)(A + (rin * 4 + u) * 4);
            const u64 p0 = pk(x0);
            const u64 p1 = pk(x1);
            fma2(acc[0][0], p0, a2.x);
            fma2(acc[0][1], p0, a2.y);
            fma2(acc[1][0], p1, a2.x);
            fma2(acc[1][1], p1, a2.y);
        }
    }
    __syncthreads();
#pragma unroll
    for (int p = 0; p < 2; ++p) {
        const float2 v01 = upk(acc[p][0]);
        const float2 v23 = upk(acc[p][1]);
        W[0 * 1024 + m0 + p] = v01.x;
        W[1 * 1024 + m0 + p] = v01.y;
        W[2 * 1024 + m0 + p] = v23.x;
        W[3 * 1024 + m0 + p] = v23.y;
    }
    __syncthreads();
}

__global__ void peps_zero_flags()
{
    g_flag[blockIdx.x * blockDim.x + threadIdx.x] = 0u;
}

__global__ __launch_bounds__(NT, 2)
void peps_half_kernel(const int* __restrict__ x, const float* __restrict__ T,
                      float* __restrict__ out)
{
    extern __shared__ float smem[];
    float* W = smem;                               // [0, 16384)
    float* As = smem + 16384;                      // 18 * 256 = 4608 floats
    int* spins = (int*)(smem + 16384 + 4608);      // 36 (+ pad)

    const int blk = blockIdx.x;
    const bool top = (blk & 1) == 0;               // pair 2b (top) / 2b+1 (bottom)
    const int b = blk >> 1;
    const int tid = threadIdx.x;

    if (tid < 36) spins[tid] = x[b * 36 + tid];
    if (tid == 0) W[0] = 1.0f;
    __syncthreads();

    // Stage this half's 18 site matrices. Processed rows r'=0,1,2 map to
    // global rows gi = r' (top) or 5-r' (bottom). Bottom swaps T's u/d strides
    // (vertical mirror); direction sequence (L2R,R2L,L2R) identical for both,
    // so the final 4096-state layouts match bit-for-bit.
    const int ustr = top ? 64 : 4;
    const int dstr = top ? 4 : 64;
    for (int c = tid; c < 18 * 8; c += NT) {
        const int sidx = c >> 3;
        const int chunk = c & 7;
        const int r = sidx / 6;
        const int st = sidx - r * 6;
        const int gi = top ? r : (5 - r);
        const int ud = (r == 0) ? 1 : 4;
        const int dd = 4;
        const bool l2r = ((r & 1) == 0);
        const int Rin  = (st == 0) ? 1 : 4;
        const int Rout = (st == 5) ? 1 : 4;
        const int K = ud * Rin;
        const int N = Rout * dd;
        const int jc = l2r ? st : (5 - st);
        const int s = spins[gi * 6 + jc];
        const float* Tb = T + (size_t)((gi * 6 + jc) * 2 + s) * 256;
        const int kn = K * N;
        for (int idx = chunk * 32; idx < min(kn, chunk * 32 + 32); ++idx) {
            int k = idx / N, n = idx - k * N;
            int rin = k / ud, u = k - rin * ud;
            int rout = n / dd, d = n - rout * dd;
            int rr = l2r ? rout : rin;
            int ll = l2r ? rin : rout;
            As[sidx * 256 + idx] = Tb[u * ustr + rr * 16 + d * dstr + ll];
        }
    }
    __syncthreads();

    // ---- Processed row 0 (ud=1, dd=4, L2R) ----
    {
        const float* A = As;
        step_b<1,    1, 16, 1, 1, 1   >(W, A + 0 * 256, tid);
        step_b<4,    4, 16, 1, 1, 4   >(W, A + 1 * 256, tid);
        step_b<16,   4, 16, 1, 1, 16  >(W, A + 2 * 256, tid);
        step_b<64,   4, 16, 1, 1, 64  >(W, A + 3 * 256, tid);
        step_b<256,  4, 16, 1, 1, 256 >(W, A + 4 * 256, tid);
        step_b<1024, 4, 4,  1, 1, 1024>(W, A + 5 * 256, tid);
    }

    // ---- Processed rows 1,2 (interior) ----
    for (int r = 1; r <= 2; ++r) {
        const float* A = As + r * 6 * 256;
        step_fast_vec<4, 10>(W, A + 0 * 256, tid);
        step_fast_vec<16, 8>(W, A + 1 * 256, tid);
        step_fast_vec<16, 6>(W, A + 2 * 256, tid);
        step_fast_vec<16, 4>(W, A + 3 * 256, tid);
        step_fast_vec<16, 2>(W, A + 4 * 256, tid);
        step_fast_last(W, A + 5 * 256, tid);
    }
    // W now holds the 4096-float boundary vector at the row2|row3 cut.

    if (top) {
        float* dst = g_vtop + (size_t)b * 4096;
        for (int i4 = tid; i4 < 1024; i4 += NT)
            ((float4*)dst)[i4] = ((const float4*)W)[i4];
        __syncthreads();                 // all V stores issued block-wide
        if (tid == 0) {
            __threadfence();             // make them device-visible
            asm volatile("st.release.gpu.global.u32 [%0], %1;"
                         :: "l"(&g_flag[b]), "r"(1u) : "memory");
        }
    } else {
        // Wait for the paired top CTA (co-resident same wave -> spin ~0).
        if (tid == 0) {
            unsigned v;
            do {
                asm volatile("ld.acquire.gpu.global.u32 %0, [%1];"
                             : "=r"(v) : "l"(&g_flag[b]) : "memory");
                if (!v) __nanosleep(64);
            } while (!v);
        }
        __syncthreads();
        __threadfence();

        const float* src = g_vtop + (size_t)b * 4096;
        float p = 0.f;
        for (int i4 = tid; i4 < 1024; i4 += NT) {
            const float4 a = ((const float4*)src)[i4];
            const float4 w = ((const float4*)W)[i4];
            p += a.x * w.x + a.y * w.y + a.z * w.z + a.w * w.w;
        }
#pragma unroll
        for (int o = 16; o; o >>= 1)
            p += __shfl_down_sync(0xFFFFFFFFu, p, o);
        if ((tid & 31) == 0) As[tid >> 5] = p;   // reuse As as scratch
        __syncthreads();
        if (tid == 0) {
            float s = 0.f;
            for (int w = 0; w < NT / 32; ++w) s += As[w];
            out[b] = s;
        }
    }
}

extern "C" void kernel_launch(void* const* d_in, const int* in_sizes, int n_in,
                              void* d_out, int out_size)
{
    const int T_ELEMS = 6 * 6 * 2 * 4 * 4 * 4 * 4;   // 73728
    const int* x;
    const float* T;
    if (in_sizes[0] == T_ELEMS) {
        T = (const float*)d_in[0];
        x = (const int*)d_in[1];
    } else {
        x = (const int*)d_in[0];
        T = (const float*)d_in[1];
    }

    const int smem_bytes = (16384 + 4608 + 64) * (int)sizeof(float);
    cudaFuncSetAttribute(peps_half_kernel,
                         cudaFuncAttributeMaxDynamicSharedMemorySize, smem_bytes);
    cudaFuncSetAttribute(peps_half_kernel,
                         cudaFuncAttributePreferredSharedMemoryCarveout, 100);

    peps_zero_flags<<<1, 1024>>>();
    peps_half_kernel<<<2 * out_size, NT, smem_bytes>>>(x, T, (float*)d_out);
}

// round 10
// speedup vs baseline: 1.0485x; 1.0485x over previous
#include <cuda_runtime.h>
#include <cuda_bf16.h>

// PEPS 6x6, D=4, phys=2, batch=1024. Row-sweep exact contraction, snake order.
// One CTA (512 threads) per config, single W buffer, 2 CTAs/SM.
// Round-8 structure; step_fast_last re-mapped (m = t, t+512) to kill its
// 4-way LDS bank conflicts (was the last smem-traffic hotspot).

#define NT 512

typedef unsigned long long u64;

__device__ __forceinline__ u64 pk(float v) {
    u64 r;
    asm("mov.b64 %0, {%1, %1};" : "=l"(r) : "f"(v));
    return r;
}
__device__ __forceinline__ void fma2(u64& d, u64 a, u64 b) {
    asm("fma.rn.f32x2 %0, %1, %2, %0;" : "+l"(d) : "l"(a), "l"(b));
}
__device__ __forceinline__ float2 upk(u64 v) {
    float2 r;
    asm("mov.b64 {%0, %1}, %2;" : "=f"(r.x), "=f"(r.y) : "l"(v));
    return r;
}

// Boundary-row step, all shape parameters compile-time.
template <int F, int K, int N, int PU, int UD, int SRIN>
__device__ __forceinline__ void step_b(
    float* __restrict__ W, const float* __restrict__ A, int tid)
{
    constexpr int TOTAL = N * F;
    constexpr int NOUT = (TOTAL + NT - 1) / NT;
    float accl[NOUT];
    int cnt = 0;
    for (int o = tid; o < TOTAL; o += NT) {
        const int n = o / F;
        const int m = o - n * F;
        const int dp = m / PU;
        const int ur = m - dp * PU;
        const int inb = dp * UD * PU + ur;
        float s = 0.f;
#pragma unroll
        for (int k = 0; k < K; ++k) {
            const int rin = k / UD;
            const int u = k - rin * UD;
            s = fmaf(W[inb + rin * SRIN + u * PU], A[k * N + n], s);
        }
        accl[cnt++] = s;
    }
    __syncthreads();
    cnt = 0;
    for (int o = tid; o < TOTAL; o += NT) {
        const int n = o / F;
        const int m = o - n * F;
        W[n * F + m] = accl[cnt++];
    }
    __syncthreads();
}

// Interior rows, steps 0..4 (proven codegen): F=1024, N=16, Pu = 1<<PSH >= 4.
template <int K, int PSH>
__device__ __forceinline__ void step_fast_vec(
    float* __restrict__ W, const float* __restrict__ A, int tid)
{
    const int g = tid >> 8;           // n-group: n = 8g..8g+7
    const int t = tid & 255;
    const int mb = t << 2;            // m-vec base
    const int dp = mb >> PSH;
    const int ur = mb & ((1 << PSH) - 1);
    const int inb = (dp << (PSH + 2)) + ur;

    u64 acc[8][2];
#pragma unroll
    for (int n = 0; n < 8; ++n) { acc[n][0] = 0ull; acc[n][1] = 0ull; }

#pragma unroll
    for (int k = 0; k < K; ++k) {
        const int off = (k >> 2) * 4096 + ((k & 3) << PSH);
        const ulonglong2 xv = *(const ulonglong2*)(W + inb + off);
        const float4 alo = *(const float4*)(A + k * 16 + g * 8);
        const float4 ahi = *(const float4*)(A + k * 16 + g * 8 + 4);
        const float av[8] = { alo.x, alo.y, alo.z, alo.w,
                              ahi.x, ahi.y, ahi.z, ahi.w };
#pragma unroll
        for (int n = 0; n < 8; ++n) {
            const u64 a2 = pk(av[n]);
            fma2(acc[n][0], xv.x, a2);
            fma2(acc[n][1], xv.y, a2);
        }
    }

    __syncthreads();
#pragma unroll
    for (int n = 0; n < 8; ++n) {
        ulonglong2 o;
        o.x = acc[n][0];
        o.y = acc[n][1];
        *(ulonglong2*)(W + (g * 8 + n) * 1024 + mb) = o;
    }
    __syncthreads();
}

// Interior rows, step 5: F=1024, N=4, K=16 (input layout rin*4096 + m*4 + u).
// Thread handles m = t and m = t+512: x LDS.128 at byte 16*t -> lanes 16B
// apart -> conflict-free coalesced loads (old 2t/2t+1 mapping was 32B-stride
// -> 4-way bank conflict on every load).
__device__ __forceinline__ void step_fast_last(
    float* __restrict__ W, const float* __restrict__ A, int tid)
{
    const int m0 = tid;
    const int m1 = tid + 512;
    u64 acc[2][2];                    // [m-slot][n-pair]
    acc[0][0] = acc[0][1] = acc[1][0] = acc[1][1] = 0ull;

#pragma unroll
    for (int rin = 0; rin < 4; ++rin) {
        const float4 xv0 = *(const float4*)(W + m0 * 4 + rin * 4096);
        const float4 xv1 = *(const float4*)(W + m1 * 4 + rin * 4096);
#pragma unroll
        for (int u = 0; u < 4; ++u) {
            const float x0 = (u == 0) ? xv0.x : (u == 1) ? xv0.y : (u == 2) ? xv0.z : xv0.w;
            const float x1 = (u == 0) ? xv1.x : (u == 1) ? xv1.y : (u == 2) ? xv1.z : xv1.w;
            const ulonglong2 a2 = *(const ulonglong2*)(A + (rin * 4 + u) * 4);
            const u64 p0 = pk(x0);
            const u64 p1 = pk(x1);
            fma2(acc[0][0], p0, a2.x);
            fma2(acc[0][1], p0, a2.y);
            fma2(acc[1][0], p1, a2.x);
            fma2(acc[1][1], p1, a2.y);
        }
    }
    __syncthreads();
#pragma unroll
    for (int p = 0; p < 2; ++p) {
        const int m = (p == 0) ? m0 : m1;
        const float2 v01 = upk(acc[p][0]);
        const float2 v23 = upk(acc[p][1]);
        W[0 * 1024 + m] = v01.x;
        W[1 * 1024 + m] = v01.y;
        W[2 * 1024 + m] = v23.x;
        W[3 * 1024 + m] = v23.y;
    }
    __syncthreads();
}

__global__ __launch_bounds__(NT, 2)
void peps_amp_kernel(const int* __restrict__ x, const float* __restrict__ T,
                     float* __restrict__ out)
{
    extern __shared__ float smem[];
    float* W = smem;                               // [0, 16384)
    float* As = smem + 16384;                      // 36 * 256 = 9216 floats
    int* spins = (int*)(smem + 16384 + 9216);      // 36 (+ pad)

    const int b = blockIdx.x;
    const int tid = threadIdx.x;

    if (tid < 36) spins[tid] = x[b * 36 + tid];
    if (tid == 0) W[0] = 1.0f;
    __syncthreads();

    // Stage ALL 36 site matrices once: As[(i*6+st)*256 + k*N + n],
    // k = rin*ud + u, n = rout*dd + d.
    for (int site = tid; site < 36 * 8; site += NT) {
        const int sidx = site >> 3;
        const int chunk = site & 7;
        const int i = sidx / 6;
        const int st = sidx - i * 6;
        const int ud = (i == 0) ? 1 : 4;
        const int dd = (i == 5) ? 1 : 4;
        const bool l2r = ((i & 1) == 0);
        const int Rin  = (st == 0) ? 1 : 4;
        const int Rout = (st == 5) ? 1 : 4;
        const int K = ud * Rin;
        const int N = Rout * dd;
        const int jc = l2r ? st : (5 - st);
        const int s = spins[i * 6 + jc];
        const float* Tb = T + (size_t)((i * 6 + jc) * 2 + s) * 256;
        const int kn = K * N;
        for (int idx = chunk * 32; idx < min(kn, chunk * 32 + 32); ++idx) {
            int k = idx / N, n = idx - k * N;
            int rin = k / ud, u = k - rin * ud;
            int rout = n / dd, d = n - rout * dd;
            int r = l2r ? rout : rin;
            int l = l2r ? rin : rout;
            As[sidx * 256 + idx] = Tb[u * 64 + r * 16 + d * 4 + l];
        }
    }
    __syncthreads();

    // ---- Row 0 (ud=1, dd=4, L->R) ----
    {
        const float* A = As;
        step_b<1,    1, 16, 1, 1, 1   >(W, A + 0 * 256, tid);
        step_b<4,    4, 16, 1, 1, 4   >(W, A + 1 * 256, tid);
        step_b<16,   4, 16, 1, 1, 16  >(W, A + 2 * 256, tid);
        step_b<64,   4, 16, 1, 1, 64  >(W, A + 3 * 256, tid);
        step_b<256,  4, 16, 1, 1, 256 >(W, A + 4 * 256, tid);
        step_b<1024, 4, 4,  1, 1, 1024>(W, A + 5 * 256, tid);
    }

    // ---- Rows 1..4 (interior) ----
    for (int i = 1; i <= 4; ++i) {
        const float* A = As + i * 6 * 256;
        step_fast_vec<4, 10>(W, A + 0 * 256, tid);
        step_fast_vec<16, 8>(W, A + 1 * 256, tid);
        step_fast_vec<16, 6>(W, A + 2 * 256, tid);
        step_fast_vec<16, 4>(W, A + 3 * 256, tid);
        step_fast_vec<16, 2>(W, A + 4 * 256, tid);
        step_fast_last(W, A + 5 * 256, tid);
    }

    // ---- Row 5 (ud=4, dd=1, R->L) ----
    {
        const float* A = As + 5 * 6 * 256;
        step_b<1024, 4,  4, 1024, 4, 4096>(W, A + 0 * 256, tid);
        step_b<256, 16,  4, 256,  4, 1024>(W, A + 1 * 256, tid);
        step_b<64,  16,  4, 64,   4, 256 >(W, A + 2 * 256, tid);
        step_b<16,  16,  4, 16,   4, 64  >(W, A + 3 * 256, tid);
        step_b<4,   16,  4, 4,    4, 16  >(W, A + 4 * 256, tid);
        step_b<1,   16,  1, 1,    4, 4   >(W, A + 5 * 256, tid);
    }

    if (tid == 0) out[b] = W[0];
}

extern "C" void kernel_launch(void* const* d_in, const int* in_sizes, int n_in,
                              void* d_out, int out_size)
{
    const int T_ELEMS = 6 * 6 * 2 * 4 * 4 * 4 * 4;   // 73728
    const int* x;
    const float* T;
    if (in_sizes[0] == T_ELEMS) {
        T = (const float*)d_in[0];
        x = (const int*)d_in[1];
    } else {
        x = (const int*)d_in[0];
        T = (const float*)d_in[1];
    }

    const int smem_bytes = (16384 + 9216 + 64) * (int)sizeof(float);
    cudaFuncSetAttribute(peps_amp_kernel,
                         cudaFuncAttributeMaxDynamicSharedMemorySize, smem_bytes);
    cudaFuncSetAttribute(peps_amp_kernel,
                         cudaFuncAttributePreferredSharedMemoryCarveout, 100);

    peps_amp_kernel<<<out_size, NT, smem_bytes>>>(x, T, (float*)d_out);
}

// round 11
// speedup vs baseline: 1.2414x; 1.1839x over previous
#include <cuda_runtime.h>
#include <cuda_bf16.h>

// PEPS 6x6, D=4, phys=2, batch=1024. Row-sweep exact contraction, snake order.
// One CTA (512 threads) per config, single W buffer, 2 CTAs/SM.
// NEW: XOR bank-swizzles on the st2->st3 and st3->st4 buffer generations to
// kill the 2-way (step 3) and 4-way (step 4) LDS bank conflicts on x loads.
//   swz1: idx ^ (((idx>>6)&3)<<4)   (u-field ^= dp&3,    PSH=4 consumer)
//   swz2: idx ^ (((idx>>5)&3)<<2)   (u-field ^= (dp>>1)&3, PSH=2 consumer)

#define NT 512

typedef unsigned long long u64;

__device__ __forceinline__ u64 pk(float v) {
    u64 r;
    asm("mov.b64 %0, {%1, %1};" : "=l"(r) : "f"(v));
    return r;
}
__device__ __forceinline__ void fma2(u64& d, u64 a, u64 b) {
    asm("fma.rn.f32x2 %0, %1, %2, %0;" : "+l"(d) : "l"(a), "l"(b));
}
__device__ __forceinline__ float2 upk(u64 v) {
    float2 r;
    asm("mov.b64 {%0, %1}, %2;" : "=f"(r.x), "=f"(r.y) : "l"(v));
    return r;
}

// Boundary-row step, all shape parameters compile-time.
template <int F, int K, int N, int PU, int UD, int SRIN>
__device__ __forceinline__ void step_b(
    float* __restrict__ W, const float* __restrict__ A, int tid)
{
    constexpr int TOTAL = N * F;
    constexpr int NOUT = (TOTAL + NT - 1) / NT;
    float accl[NOUT];
    int cnt = 0;
    for (int o = tid; o < TOTAL; o += NT) {
        const int n = o / F;
        const int m = o - n * F;
        const int dp = m / PU;
        const int ur = m - dp * PU;
        const int inb = dp * UD * PU + ur;
        float s = 0.f;
#pragma unroll
        for (int k = 0; k < K; ++k) {
            const int rin = k / UD;
            const int u = k - rin * UD;
            s = fmaf(W[inb + rin * SRIN + u * PU], A[k * N + n], s);
        }
        accl[cnt++] = s;
    }
    __syncthreads();
    cnt = 0;
    for (int o = tid; o < TOTAL; o += NT) {
        const int n = o / F;
        const int m = o - n * F;
        W[n * F + m] = accl[cnt++];
    }
    __syncthreads();
}

// Interior rows, steps 0..4: F=1024, N=16, Pu = 1<<PSH >= 4.
// SWZI/SWZO in {0,1,2}: swizzle id applied to the input/output buffer.
//   1: idx ^ (((idx>>6)&3)<<4)    2: idx ^ (((idx>>5)&3)<<2)
// For loads the xor reduces to permuting the per-k u-offset by a per-thread
// constant s (inb's u-field bits are zero). For stores the xor term is a
// per-thread constant on the dest index; 16B blocks move as units.
template <int K, int PSH, int SWZI, int SWZO>
__device__ __forceinline__ void step_fast_vec(
    float* __restrict__ W, const float* __restrict__ A, int tid)
{
    const int g = tid >> 8;           // n-group: n = 8g..8g+7
    const int t = tid & 255;
    const int mb = t << 2;            // m-vec base
    const int dp = mb >> PSH;
    const int ur = mb & ((1 << PSH) - 1);
    const int inb = (dp << (PSH + 2)) + ur;

    // Input-side u permutation constant.
    const int si = (SWZI == 1) ? (dp & 3) : (SWZI == 2) ? ((dp >> 1) & 3) : 0;
    // Output-side xor term on dest index (bits of mb select it).
    const int so = (SWZO == 1) ? (((mb >> 6) & 3) << 4)
                 : (SWZO == 2) ? (((mb >> 5) & 3) << 2) : 0;

    u64 acc[8][2];
#pragma unroll
    for (int n = 0; n < 8; ++n) { acc[n][0] = 0ull; acc[n][1] = 0ull; }

#pragma unroll
    for (int k = 0; k < K; ++k) {
        const int off = (k >> 2) * 4096 + (((k & 3) ^ si) << PSH);
        const ulonglong2 xv = *(const ulonglong2*)(W + inb + off);
        const float4 alo = *(const float4*)(A + k * 16 + g * 8);
        const float4 ahi = *(const float4*)(A + k * 16 + g * 8 + 4);
        const float av[8] = { alo.x, alo.y, alo.z, alo.w,
                              ahi.x, ahi.y, ahi.z, ahi.w };
#pragma unroll
        for (int n = 0; n < 8; ++n) {
            const u64 a2 = pk(av[n]);
            fma2(acc[n][0], xv.x, a2);
            fma2(acc[n][1], xv.y, a2);
        }
    }

    __syncthreads();
#pragma unroll
    for (int n = 0; n < 8; ++n) {
        ulonglong2 o;
        o.x = acc[n][0];
        o.y = acc[n][1];
        *(ulonglong2*)(W + (((g * 8 + n) * 1024 + mb) ^ so)) = o;
    }
    __syncthreads();
}

// Interior rows, step 5: F=1024, N=4, K=16 (input layout rin*4096 + m*4 + u,
// unswizzled). m = t and t+512: conflict-free.
__device__ __forceinline__ void step_fast_last(
    float* __restrict__ W, const float* __restrict__ A, int tid)
{
    const int m0 = tid;
    const int m1 = tid + 512;
    u64 acc[2][2];                    // [m-slot][n-pair]
    acc[0][0] = acc[0][1] = acc[1][0] = acc[1][1] = 0ull;

#pragma unroll
    for (int rin = 0; rin < 4; ++rin) {
        const float4 xv0 = *(const float4*)(W + m0 * 4 + rin * 4096);
        const float4 xv1 = *(const float4*)(W + m1 * 4 + rin * 4096);
#pragma unroll
        for (int u = 0; u < 4; ++u) {
            const float x0 = (u == 0) ? xv0.x : (u == 1) ? xv0.y : (u == 2) ? xv0.z : xv0.w;
            const float x1 = (u == 0) ? xv1.x : (u == 1) ? xv1.y : (u == 2) ? xv1.z : xv1.w;
            const ulonglong2 a2 = *(const ulonglong2*)(A + (rin * 4 + u) * 4);
            const u64 p0 = pk(x0);
            const u64 p1 = pk(x1);
            fma2(acc[0][0], p0, a2.x);
            fma2(acc[0][1], p0, a2.y);
            fma2(acc[1][0], p1, a2.x);
            fma2(acc[1][1], p1, a2.y);
        }
    }
    __syncthreads();
#pragma unroll
    for (int p = 0; p < 2; ++p) {
        const int m = (p == 0) ? m0 : m1;
        const float2 v01 = upk(acc[p][0]);
        const float2 v23 = upk(acc[p][1]);
        W[0 * 1024 + m] = v01.x;
        W[1 * 1024 + m] = v01.y;
        W[2 * 1024 + m] = v23.x;
        W[3 * 1024 + m] = v23.y;
    }
    __syncthreads();
}

__global__ __launch_bounds__(NT, 2)
void peps_amp_kernel(const int* __restrict__ x, const float* __restrict__ T,
                     float* __restrict__ out)
{
    extern __shared__ float smem[];
    float* W = smem;                               // [0, 16384)
    float* As = smem + 16384;                      // 36 * 256 = 9216 floats
    int* spins = (int*)(smem + 16384 + 9216);      // 36 (+ pad)

    const int b = blockIdx.x;
    const int tid = threadIdx.x;

    if (tid < 36) spins[tid] = x[b * 36 + tid];
    if (tid == 0) W[0] = 1.0f;
    __syncthreads();

    // Stage ALL 36 site matrices once: As[(i*6+st)*256 + k*N + n],
    // k = rin*ud + u, n = rout*dd + d.
    for (int site = tid; site < 36 * 8; site += NT) {
        const int sidx = site >> 3;
        const int chunk = site & 7;
        const int i = sidx / 6;
        const int st = sidx - i * 6;
        const int ud = (i == 0) ? 1 : 4;
        const int dd = (i == 5) ? 1 : 4;
        const bool l2r = ((i & 1) == 0);
        const int Rin  = (st == 0) ? 1 : 4;
        const int Rout = (st == 5) ? 1 : 4;
        const int K = ud * Rin;
        const int N = Rout * dd;
        const int jc = l2r ? st : (5 - st);
        const int s = spins[i * 6 + jc];
        const float* Tb = T + (size_t)((i * 6 + jc) * 2 + s) * 256;
        const int kn = K * N;
        for (int idx = chunk * 32; idx < min(kn, chunk * 32 + 32); ++idx) {
            int k = idx / N, n = idx - k * N;
            int rin = k / ud, u = k - rin * ud;
            int rout = n / dd, d = n - rout * dd;
            int r = l2r ? rout : rin;
            int l = l2r ? rin : rout;
            As[sidx * 256 + idx] = Tb[u * 64 + r * 16 + d * 4 + l];
        }
    }
    __syncthreads();

    // ---- Row 0 (ud=1, dd=4, L->R) ----
    {
        const float* A = As;
        step_b<1,    1, 16, 1, 1, 1   >(W, A + 0 * 256, tid);
        step_b<4,    4, 16, 1, 1, 4   >(W, A + 1 * 256, tid);
        step_b<16,   4, 16, 1, 1, 16  >(W, A + 2 * 256, tid);
        step_b<64,   4, 16, 1, 1, 64  >(W, A + 3 * 256, tid);
        step_b<256,  4, 16, 1, 1, 256 >(W, A + 4 * 256, tid);
        step_b<1024, 4, 4,  1, 1, 1024>(W, A + 5 * 256, tid);
    }

    // ---- Rows 1..4 (interior) ----
    for (int i = 1; i <= 4; ++i) {
        const float* A = As + i * 6 * 256;
        step_fast_vec<4, 10, 0, 0>(W, A + 0 * 256, tid);
        step_fast_vec<16, 8, 0, 0>(W, A + 1 * 256, tid);
        step_fast_vec<16, 6, 0, 1>(W, A + 2 * 256, tid);   // out: swz1
        step_fast_vec<16, 4, 1, 2>(W, A + 3 * 256, tid);   // in: swz1, out: swz2
        step_fast_vec<16, 2, 2, 0>(W, A + 4 * 256, tid);   // in: swz2
        step_fast_last(W, A + 5 * 256, tid);
    }

    // ---- Row 5 (ud=4, dd=1, R->L) ----
    {
        const float* A = As + 5 * 6 * 256;
        step_b<1024, 4,  4, 1024, 4, 4096>(W, A + 0 * 256, tid);
        step_b<256, 16,  4, 256,  4, 1024>(W, A + 1 * 256, tid);
        step_b<64,  16,  4, 64,   4, 256 >(W, A + 2 * 256, tid);
        step_b<16,  16,  4, 16,   4, 64  >(W, A + 3 * 256, tid);
        step_b<4,   16,  4, 4,    4, 16  >(W, A + 4 * 256, tid);
        step_b<1,   16,  1, 1,    4, 4   >(W, A + 5 * 256, tid);
    }

    if (tid == 0) out[b] = W[0];
}

extern "C" void kernel_launch(void* const* d_in, const int* in_sizes, int n_in,
                              void* d_out, int out_size)
{
    const int T_ELEMS = 6 * 6 * 2 * 4 * 4 * 4 * 4;   // 73728
    const int* x;
    const float* T;
    if (in_sizes[0] == T_ELEMS) {
        T = (const float*)d_in[0];
        x = (const int*)d_in[1];
    } else {
        x = (const int*)d_in[0];
        T = (const float*)d_in[1];
    }

    const int smem_bytes = (16384 + 9216 + 64) * (int)sizeof(float);
    cudaFuncSetAttribute(peps_amp_kernel,
                         cudaFuncAttributeMaxDynamicSharedMemorySize, smem_bytes);
    cudaFuncSetAttribute(peps_amp_kernel,
                         cudaFuncAttributePreferredSharedMemoryCarveout, 100);

    peps_amp_kernel<<<out_size, NT, smem_bytes>>>(x, T, (float*)d_out);
}

// round 12
// speedup vs baseline: 1.2427x; 1.0010x over previous
#include <cuda_runtime.h>
#include <cuda_bf16.h>

// PEPS 6x6, D=4, phys=2, batch=1024. Row-sweep exact contraction, snake order.
// One CTA (512 threads) per config, single W buffer, 2 CTAs/SM.
// NEW: XOR bank-swizzles on the st2->st3 and st3->st4 buffer generations to
// kill the 2-way (step 3) and 4-way (step 4) LDS bank conflicts on x loads.
//   swz1: idx ^ (((idx>>6)&3)<<4)   (u-field ^= dp&3,    PSH=4 consumer)
//   swz2: idx ^ (((idx>>5)&3)<<2)   (u-field ^= (dp>>1)&3, PSH=2 consumer)

#define NT 512

typedef unsigned long long u64;

__device__ __forceinline__ u64 pk(float v) {
    u64 r;
    asm("mov.b64 %0, {%1, %1};" : "=l"(r) : "f"(v));
    return r;
}
__device__ __forceinline__ void fma2(u64& d, u64 a, u64 b) {
    asm("fma.rn.f32x2 %0, %1, %2, %0;" : "+l"(d) : "l"(a), "l"(b));
}
__device__ __forceinline__ float2 upk(u64 v) {
    float2 r;
    asm("mov.b64 {%0, %1}, %2;" : "=f"(r.x), "=f"(r.y) : "l"(v));
    return r;
}

// Boundary-row step, all shape parameters compile-time.
template <int F, int K, int N, int PU, int UD, int SRIN>
__device__ __forceinline__ void step_b(
    float* __restrict__ W, const float* __restrict__ A, int tid)
{
    constexpr int TOTAL = N * F;
    constexpr int NOUT = (TOTAL + NT - 1) / NT;
    float accl[NOUT];
    int cnt = 0;
    for (int o = tid; o < TOTAL; o += NT) {
        const int n = o / F;
        const int m = o - n * F;
        const int dp = m / PU;
        const int ur = m - dp * PU;
        const int inb = dp * UD * PU + ur;
        float s = 0.f;
#pragma unroll
        for (int k = 0; k < K; ++k) {
            const int rin = k / UD;
            const int u = k - rin * UD;
            s = fmaf(W[inb + rin * SRIN + u * PU], A[k * N + n], s);
        }
        accl[cnt++] = s;
    }
    __syncthreads();
    cnt = 0;
    for (int o = tid; o < TOTAL; o += NT) {
        const int n = o / F;
        const int m = o - n * F;
        W[n * F + m] = accl[cnt++];
    }
    __syncthreads();
}

// Interior rows, steps 0..4: F=1024, N=16, Pu = 1<<PSH >= 4.
// SWZI/SWZO in {0,1,2}: swizzle id applied to the input/output buffer.
//   1: idx ^ (((idx>>6)&3)<<4)    2: idx ^ (((idx>>5)&3)<<2)
// For loads the xor reduces to permuting the per-k u-offset by a per-thread
// constant s (inb's u-field bits are zero). For stores the xor term is a
// per-thread constant on the dest index; 16B blocks move as units.
template <int K, int PSH, int SWZI, int SWZO>
__device__ __forceinline__ void step_fast_vec(
    float* __restrict__ W, const float* __restrict__ A, int tid)
{
    const int g = tid >> 8;           // n-group: n = 8g..8g+7
    const int t = tid & 255;
    const int mb = t << 2;            // m-vec base
    const int dp = mb >> PSH;
    const int ur = mb & ((1 << PSH) - 1);
    const int inb = (dp << (PSH + 2)) + ur;

    // Input-side u permutation constant.
    const int si = (SWZI == 1) ? (dp & 3) : (SWZI == 2) ? ((dp >> 1) & 3) : 0;
    // Output-side xor term on dest index (bits of mb select it).
    const int so = (SWZO == 1) ? (((mb >> 6) & 3) << 4)
                 : (SWZO == 2) ? (((mb >> 5) & 3) << 2) : 0;

    u64 acc[8][2];
#pragma unroll
    for (int n = 0; n < 8; ++n) { acc[n][0] = 0ull; acc[n][1] = 0ull; }

#pragma unroll
    for (int k = 0; k < K; ++k) {
        const int off = (k >> 2) * 4096 + (((k & 3) ^ si) << PSH);
        const ulonglong2 xv = *(const ulonglong2*)(W + inb + off);
        const float4 alo = *(const float4*)(A + k * 16 + g * 8);
        const float4 ahi = *(const float4*)(A + k * 16 + g * 8 + 4);
        const float av[8] = { alo.x, alo.y, alo.z, alo.w,
                              ahi.x, ahi.y, ahi.z, ahi.w };
#pragma unroll
        for (int n = 0; n < 8; ++n) {
            const u64 a2 = pk(av[n]);
            fma2(acc[n][0], xv.x, a2);
            fma2(acc[n][1], xv.y, a2);
        }
    }

    __syncthreads();
#pragma unroll
    for (int n = 0; n < 8; ++n) {
        ulonglong2 o;
        o.x = acc[n][0];
        o.y = acc[n][1];
        *(ulonglong2*)(W + (((g * 8 + n) * 1024 + mb) ^ so)) = o;
    }
    __syncthreads();
}

// Interior rows, step 5: F=1024, N=4, K=16 (input layout rin*4096 + m*4 + u,
// unswizzled). m = t and t+512: conflict-free.
__device__ __forceinline__ void step_fast_last(
    float* __restrict__ W, const float* __restrict__ A, int tid)
{
    const int m0 = tid;
    const int m1 = tid + 512;
    u64 acc[2][2];                    // [m-slot][n-pair]
    acc[0][0] = acc[0][1] = acc[1][0] = acc[1][1] = 0ull;

#pragma unroll
    for (int rin = 0; rin < 4; ++rin) {
        const float4 xv0 = *(const float4*)(W + m0 * 4 + rin * 4096);
        const float4 xv1 = *(const float4*)(W + m1 * 4 + rin * 4096);
#pragma unroll
        for (int u = 0; u < 4; ++u) {
            const float x0 = (u == 0) ? xv0.x : (u == 1) ? xv0.y : (u == 2) ? xv0.z : xv0.w;
            const float x1 = (u == 0) ? xv1.x : (u == 1) ? xv1.y : (u == 2) ? xv1.z : xv1.w;
            const ulonglong2 a2 = *(const ulonglong2*)(A + (rin * 4 + u) * 4);
            const u64 p0 = pk(x0);
            const u64 p1 = pk(x1);
            fma2(acc[0][0], p0, a2.x);
            fma2(acc[0][1], p0, a2.y);
            fma2(acc[1][0], p1, a2.x);
            fma2(acc[1][1], p1, a2.y);
        }
    }
    __syncthreads();
#pragma unroll
    for (int p = 0; p < 2; ++p) {
        const int m = (p == 0) ? m0 : m1;
        const float2 v01 = upk(acc[p][0]);
        const float2 v23 = upk(acc[p][1]);
        W[0 * 1024 + m] = v01.x;
        W[1 * 1024 + m] = v01.y;
        W[2 * 1024 + m] = v23.x;
        W[3 * 1024 + m] = v23.y;
    }
    __syncthreads();
}

__global__ __launch_bounds__(NT, 2)
void peps_amp_kernel(const int* __restrict__ x, const float* __restrict__ T,
                     float* __restrict__ out)
{
    extern __shared__ float smem[];
    float* W = smem;                               // [0, 16384)
    float* As = smem + 16384;                      // 36 * 256 = 9216 floats
    int* spins = (int*)(smem + 16384 + 9216);      // 36 (+ pad)

    const int b = blockIdx.x;
    const int tid = threadIdx.x;

    if (tid < 36) spins[tid] = x[b * 36 + tid];
    if (tid == 0) W[0] = 1.0f;
    __syncthreads();

    // Stage ALL 36 site matrices once: As[(i*6+st)*256 + k*N + n],
    // k = rin*ud + u, n = rout*dd + d.
    for (int site = tid; site < 36 * 8; site += NT) {
        const int sidx = site >> 3;
        const int chunk = site & 7;
        const int i = sidx / 6;
        const int st = sidx - i * 6;
        const int ud = (i == 0) ? 1 : 4;
        const int dd = (i == 5) ? 1 : 4;
        const bool l2r = ((i & 1) == 0);
        const int Rin  = (st == 0) ? 1 : 4;
        const int Rout = (st == 5) ? 1 : 4;
        const int K = ud * Rin;
        const int N = Rout * dd;
        const int jc = l2r ? st : (5 - st);
        const int s = spins[i * 6 + jc];
        const float* Tb = T + (size_t)((i * 6 + jc) * 2 + s) * 256;
        const int kn = K * N;
        for (int idx = chunk * 32; idx < min(kn, chunk * 32 + 32); ++idx) {
            int k = idx / N, n = idx - k * N;
            int rin = k / ud, u = k - rin * ud;
            int rout = n / dd, d = n - rout * dd;
            int r = l2r ? rout : rin;
            int l = l2r ? rin : rout;
            As[sidx * 256 + idx] = Tb[u * 64 + r * 16 + d * 4 + l];
        }
    }
    __syncthreads();

    // ---- Row 0 (ud=1, dd=4, L->R) ----
    {
        const float* A = As;
        step_b<1,    1, 16, 1, 1, 1   >(W, A + 0 * 256, tid);
        step_b<4,    4, 16, 1, 1, 4   >(W, A + 1 * 256, tid);
        step_b<16,   4, 16, 1, 1, 16  >(W, A + 2 * 256, tid);
        step_b<64,   4, 16, 1, 1, 64  >(W, A + 3 * 256, tid);
        step_b<256,  4, 16, 1, 1, 256 >(W, A + 4 * 256, tid);
        step_b<1024, 4, 4,  1, 1, 1024>(W, A + 5 * 256, tid);
    }

    // ---- Rows 1..4 (interior) ----
    for (int i = 1; i <= 4; ++i) {
        const float* A = As + i * 6 * 256;
        step_fast_vec<4, 10, 0, 0>(W, A + 0 * 256, tid);
        step_fast_vec<16, 8, 0, 0>(W, A + 1 * 256, tid);
        step_fast_vec<16, 6, 0, 1>(W, A + 2 * 256, tid);   // out: swz1
        step_fast_vec<16, 4, 1, 2>(W, A + 3 * 256, tid);   // in: swz1, out: swz2
        step_fast_vec<16, 2, 2, 0>(W, A + 4 * 256, tid);   // in: swz2
        step_fast_last(W, A + 5 * 256, tid);
    }

    // ---- Row 5 (ud=4, dd=1, R->L) ----
    {
        const float* A = As + 5 * 6 * 256;
        step_b<1024, 4,  4, 1024, 4, 4096>(W, A + 0 * 256, tid);
        step_b<256, 16,  4, 256,  4, 1024>(W, A + 1 * 256, tid);
        step_b<64,  16,  4, 64,   4, 256 >(W, A + 2 * 256, tid);
        step_b<16,  16,  4, 16,   4, 64  >(W, A + 3 * 256, tid);
        step_b<4,   16,  4, 4,    4, 16  >(W, A + 4 * 256, tid);
        step_b<1,   16,  1, 1,    4, 4   >(W, A + 5 * 256, tid);
    }

    if (tid == 0) out[b] = W[0];
}

extern "C" void kernel_launch(void* const* d_in, const int* in_sizes, int n_in,
                              void* d_out, int out_size)
{
    const int T_ELEMS = 6 * 6 * 2 * 4 * 4 * 4 * 4;   // 73728
    const int* x;
    const float* T;
    if (in_sizes[0] == T_ELEMS) {
        T = (const float*)d_in[0];
        x = (const int*)d_in[1];
    } else {
        x = (const int*)d_in[0];
        T = (const float*)d_in[1];
    }

    const int smem_bytes = (16384 + 9216 + 64) * (int)sizeof(float);
    cudaFuncSetAttribute(peps_amp_kernel,
                         cudaFuncAttributeMaxDynamicSharedMemorySize, smem_bytes);
    cudaFuncSetAttribute(peps_amp_kernel,
                         cudaFuncAttributePreferredSharedMemoryCarveout, 100);

    peps_amp_kernel<<<out_size, NT, smem_bytes>>>(x, T, (float*)d_out);
}